// round 9
// baseline (speedup 1.0000x reference)
#include <cuda_runtime.h>
#include <math_constants.h>

// Split-K persistent MAM-GEMM, single launch, in-kernel finisher merge.
// 128 output tiles of 128x128 x 8 K-splits = 1024 items over 148 persistent
// CTAs (98.8% balance). Fat TM8xTN8 microtile. The finisher merge lives in a
// __noinline__ device function so its register usage cannot inflate the hot
// loop's allocation (R8 lesson: inlined merge -> 255 regs -> spills).

#define TBM 128
#define TBN 128
#define BK  16
#define TM  8
#define TN  8
#define SA  132     // 132*4 % 16 == 0 -> LDS.128 aligned
#define NUM_SMS 148
#define SPLITS  8
#define THREADS 256

#define MM 2048
#define NN 1024
#define NTILES ((MM / TBM) * (NN / TBN))   // 128

__device__ float g_mx[SPLITS][MM * NN];    // 64 MB
__device__ float g_mn[SPLITS][MM * NN];    // 64 MB
__device__ unsigned int g_cnt[NTILES];     // zeroed at load; finisher resets -> replay-safe

// Cold path: merge 8 partials + bias -> C for one 128x128 tile.
// __noinline__ so ptxas allocates it separately from the hot mainloop.
__device__ __noinline__ void finish_tile(float* __restrict__ C,
                                         const float* __restrict__ bias,
                                         int N, int rowbase, int colbase, int tid)
{
#pragma unroll 1
    for (int it = 0; it < 16; ++it) {
        const int e = it * 1024 + tid * 4;
        const int r = e >> 7;
        const int c = e & 127;
        const size_t off = (size_t)(rowbase + r) * N + colbase + c;

        float4 xm = *(const float4*)(g_mx[0] + off);
        float4 nm = *(const float4*)(g_mn[0] + off);
#pragma unroll 1
        for (int s = 1; s < SPLITS; ++s) {
            float4 xs = *(const float4*)(g_mx[s] + off);
            float4 ns = *(const float4*)(g_mn[s] + off);
            xm.x = fmaxf(xm.x, xs.x); xm.y = fmaxf(xm.y, xs.y);
            xm.z = fmaxf(xm.z, xs.z); xm.w = fmaxf(xm.w, xs.w);
            nm.x = fminf(nm.x, ns.x); nm.y = fminf(nm.y, ns.y);
            nm.z = fminf(nm.z, ns.z); nm.w = fminf(nm.w, ns.w);
        }
        float4 bv = *(const float4*)&bias[colbase + c];
        float4 o;
        o.x = xm.x + nm.x + bv.x;
        o.y = xm.y + nm.y + bv.y;
        o.z = xm.z + nm.z + bv.z;
        o.w = xm.w + nm.w + bv.w;
        *(float4*)(C + off) = o;
    }
}

__global__ __launch_bounds__(THREADS, 1)
void mam_kernel(const float* __restrict__ A,    // [M, K]
                const float* __restrict__ W,    // [N, K]
                const float* __restrict__ bias, // [N]
                float* __restrict__ C,          // [M, N]
                int M, int N, int K)
{
    __shared__ float As[2][BK * SA];  // As[buf][k*SA + m]
    __shared__ float Bs[2][BK * SA];  // Bs[buf][k*SA + n]
    __shared__ unsigned int s_old;

    const int tid = threadIdx.x;
    const int tx  = tid & 15;    // 16 col-groups of TN=8 -> 128 cols
    const int ty  = tid >> 4;    // 16 row-groups of TM=8 -> 128 rows

    // staging: 128x16 floats per operand = 256 threads x 2 float4 (rows lrow, lrow+64)
    const int lrow = tid >> 2;        // 0..63
    const int lcol = (tid & 3) * 4;   // 0,4,8,12

    const int tilesN = N / TBN;                   // 8
    const int nTiles = (M / TBM) * tilesN;        // 128
    const int nItems = nTiles * SPLITS;           // 1024
    const int kPart  = K / SPLITS;                // 128
    const int nK     = kPart / BK;                // 8

    for (int t = blockIdx.x; t < nItems; t += NUM_SMS) {
        const int tile  = t & (nTiles - 1);
        const int split = t >> 7;
        const int mi = tile >> 3;
        const int ni = tile & 7;
        const int kbase = split * kPart;

        const float* Aptr = A + (size_t)(mi * TBM + lrow) * K + kbase + lcol;
        const float* Wptr = W + (size_t)(ni * TBN + lrow) * K + kbase + lcol;
        const size_t rowskip = (size_t)64 * K;

        float mx[TM][TN], mn[TM][TN];
#pragma unroll
        for (int i = 0; i < TM; ++i)
#pragma unroll
            for (int j = 0; j < TN; ++j) {
                mx[i][j] = -CUDART_INF_F;
                mn[i][j] =  CUDART_INF_F;
            }

        // ---- prologue: stage k-slice 0 into buf 0 ----
        float4 pa0 = *(const float4*)(Aptr);
        float4 pa1 = *(const float4*)(Aptr + rowskip);
        float4 pb0 = *(const float4*)(Wptr);
        float4 pb1 = *(const float4*)(Wptr + rowskip);
        {
            float* as = As[0]; float* bs = Bs[0];
            as[(lcol + 0) * SA + lrow] = pa0.x;
            as[(lcol + 1) * SA + lrow] = pa0.y;
            as[(lcol + 2) * SA + lrow] = pa0.z;
            as[(lcol + 3) * SA + lrow] = pa0.w;
            as[(lcol + 0) * SA + lrow + 64] = pa1.x;
            as[(lcol + 1) * SA + lrow + 64] = pa1.y;
            as[(lcol + 2) * SA + lrow + 64] = pa1.z;
            as[(lcol + 3) * SA + lrow + 64] = pa1.w;
            bs[(lcol + 0) * SA + lrow] = pb0.x;
            bs[(lcol + 1) * SA + lrow] = pb0.y;
            bs[(lcol + 2) * SA + lrow] = pb0.z;
            bs[(lcol + 3) * SA + lrow] = pb0.w;
            bs[(lcol + 0) * SA + lrow + 64] = pb1.x;
            bs[(lcol + 1) * SA + lrow + 64] = pb1.y;
            bs[(lcol + 2) * SA + lrow + 64] = pb1.z;
            bs[(lcol + 3) * SA + lrow + 64] = pb1.w;
        }
        __syncthreads();

        for (int kt = 0; kt < nK; ++kt) {
            const int buf = kt & 1;

            if (kt + 1 < nK) {
                const int k0 = (kt + 1) * BK;
                pa0 = *(const float4*)(Aptr + k0);
                pa1 = *(const float4*)(Aptr + rowskip + k0);
                pb0 = *(const float4*)(Wptr + k0);
                pb1 = *(const float4*)(Wptr + rowskip + k0);
            }

            const float* as = As[buf];
            const float* bs = Bs[buf];
#pragma unroll 8
            for (int k = 0; k < BK; ++k) {
                float a[TM], b[TN];
                *(float4*)&a[0] = *(const float4*)&as[k * SA + ty * TM];
                *(float4*)&a[4] = *(const float4*)&as[k * SA + ty * TM + 4];
                *(float4*)&b[0] = *(const float4*)&bs[k * SA + tx * TN];
                *(float4*)&b[4] = *(const float4*)&bs[k * SA + tx * TN + 4];
#pragma unroll
                for (int i = 0; i < TM; ++i)
#pragma unroll
                    for (int j = 0; j < TN; ++j) {
                        float p = a[i] * b[j];
                        mx[i][j] = fmaxf(mx[i][j], p);
                        mn[i][j] = fminf(mn[i][j], p);
                    }
            }

            if (kt + 1 < nK) {
                float* asw = As[buf ^ 1]; float* bsw = Bs[buf ^ 1];
                asw[(lcol + 0) * SA + lrow] = pa0.x;
                asw[(lcol + 1) * SA + lrow] = pa0.y;
                asw[(lcol + 2) * SA + lrow] = pa0.z;
                asw[(lcol + 3) * SA + lrow] = pa0.w;
                asw[(lcol + 0) * SA + lrow + 64] = pa1.x;
                asw[(lcol + 1) * SA + lrow + 64] = pa1.y;
                asw[(lcol + 2) * SA + lrow + 64] = pa1.z;
                asw[(lcol + 3) * SA + lrow + 64] = pa1.w;
                bsw[(lcol + 0) * SA + lrow] = pb0.x;
                bsw[(lcol + 1) * SA + lrow] = pb0.y;
                bsw[(lcol + 2) * SA + lrow] = pb0.z;
                bsw[(lcol + 3) * SA + lrow] = pb0.w;
                bsw[(lcol + 0) * SA + lrow + 64] = pb1.x;
                bsw[(lcol + 1) * SA + lrow + 64] = pb1.y;
                bsw[(lcol + 2) * SA + lrow + 64] = pb1.z;
                bsw[(lcol + 3) * SA + lrow + 64] = pb1.w;
                __syncthreads();
            }
        }

        // ---- epilogue: exclusive-owner partial stores ----
        const int row0 = mi * TBM + ty * TM;
        const int col0 = ni * TBN + tx * TN;
        float* mxp = g_mx[split] + (size_t)row0 * N + col0;
        float* mnp = g_mn[split] + (size_t)row0 * N + col0;
#pragma unroll
        for (int i = 0; i < TM; ++i) {
            *(float4*)(mxp + (size_t)i * N)     = make_float4(mx[i][0], mx[i][1], mx[i][2], mx[i][3]);
            *(float4*)(mxp + (size_t)i * N + 4) = make_float4(mx[i][4], mx[i][5], mx[i][6], mx[i][7]);
            *(float4*)(mnp + (size_t)i * N)     = make_float4(mn[i][0], mn[i][1], mn[i][2], mn[i][3]);
            *(float4*)(mnp + (size_t)i * N + 4) = make_float4(mn[i][4], mn[i][5], mn[i][6], mn[i][7]);
        }

        // ---- arrival protocol ----
        __threadfence();                 // release partial stores (gpu scope)
        __syncthreads();                 // all threads done (also orders smem reuse)
        if (tid == 0) s_old = atomicAdd(&g_cnt[tile], 1u);
        __syncthreads();

        if (s_old == SPLITS - 1) {
            __threadfence();             // acquire other CTAs' partials
            finish_tile(C, bias, N, mi * TBM, ni * TBN, tid);
            if (tid == 0) g_cnt[tile] = 0;   // reset for next graph replay
        }
    }
}

extern "C" void kernel_launch(void* const* d_in, const int* in_sizes, int n_in,
                              void* d_out, int out_size)
{
    const float* x    = (const float*)d_in[0];   // [M, K]
    const float* w    = (const float*)d_in[1];   // [N, K]
    const float* bias = (const float*)d_in[2];   // [N]
    float* out = (float*)d_out;

    const int N = in_sizes[2];                  // 1024
    const int K = in_sizes[1] / N;              // 1024
    const int M = in_sizes[0] / K;              // 2048

    mam_kernel<<<NUM_SMS, THREADS>>>(x, w, bias, out, M, N, K);
}

// round 10
// speedup vs baseline: 1.2314x; 1.2314x over previous
#include <cuda_runtime.h>
#include <math_constants.h>

// Split-K persistent MAM-GEMM, single launch, warp-granular finisher merge.
// 256 tiles of 128x64 x 4 K-splits = 1024 items over 148 persistent CTAs
// (98.8% balance). TM8xTN4 microtile (R7 proven: 150 regs, no spills).
// BK=32 halves barrier/loop overhead vs R7. Arrival is counted per WARP
// (32 warps/tile): the last 8 arriving warps each merge 1/8 of the tile,
// with no extra CTA-wide __syncthreads in the protocol.

#define TBM 128
#define TBN 64
#define BK  32
#define TM  8
#define TN  4
#define SA  132     // 132*4 % 16 == 0 -> LDS.128 aligned
#define SB  68      // 68*4  % 16 == 0 -> LDS.128 aligned
#define NUM_SMS 148
#define SPLITS  4
#define THREADS 256
#define WARPS_PER_TILE (SPLITS * (THREADS / 32))   // 32

#define MM 2048
#define NN 1024
#define NTILES ((MM / TBM) * (NN / TBN))   // 256

__device__ float g_mx[SPLITS][MM * NN];    // 32 MB
__device__ float g_mn[SPLITS][MM * NN];    // 32 MB
__device__ unsigned int g_cnt[NTILES];     // zeroed at load; last warp resets -> replay-safe

__global__ __launch_bounds__(THREADS, 1)
void mam_kernel(const float* __restrict__ A,    // [M, K]
                const float* __restrict__ W,    // [N, K]
                const float* __restrict__ bias, // [N]
                float* __restrict__ C,          // [M, N]
                int M, int N, int K)
{
    __shared__ float As[2][BK * SA];  // As[buf][k*SA + m]
    __shared__ float Bs[2][BK * SB];  // Bs[buf][k*SB + n]

    const int tid  = threadIdx.x;
    const int lane = tid & 31;
    const int tx   = tid & 15;    // 16 col-groups of TN=4 -> 64 cols
    const int ty   = tid >> 4;    // 16 row-groups of TM=8 -> 128 rows

    // A staging: 128x32 floats = 256 threads x 4 float4 (rows arow+{0,32,64,96})
    const int arow = tid >> 3;        // 0..31
    const int akc  = (tid & 7) * 4;   // 0,4,...,28
    // B staging: 64x32 floats = 256 threads x 2 float4 (rows arow+{0,32})
    const int tilesN = N / TBN;                   // 16
    const int nTiles = (M / TBM) * tilesN;        // 256
    const int nItems = nTiles * SPLITS;           // 1024
    const int kPart  = K / SPLITS;                // 256
    const int nK     = kPart / BK;                // 8

    for (int t = blockIdx.x; t < nItems; t += NUM_SMS) {
        const int tile  = t & (nTiles - 1);
        const int split = t >> 8;
        const int mi = tile >> 4;
        const int ni = tile & 15;
        const int kbase = split * kPart;

        const float* Aptr = A + (size_t)(mi * TBM + arow) * K + kbase + akc;
        const float* Wptr = W + (size_t)(ni * TBN + arow) * K + kbase + akc;
        const size_t skipA = (size_t)32 * K;

        float mx[TM][TN], mn[TM][TN];
#pragma unroll
        for (int i = 0; i < TM; ++i)
#pragma unroll
            for (int j = 0; j < TN; ++j) {
                mx[i][j] = -CUDART_INF_F;
                mn[i][j] =  CUDART_INF_F;
            }

        float4 pa[4], pb[2];

        // ---- prologue: stage k-slice 0 into buf 0 ----
#pragma unroll
        for (int r = 0; r < 4; ++r) pa[r] = *(const float4*)(Aptr + r * skipA);
#pragma unroll
        for (int r = 0; r < 2; ++r) pb[r] = *(const float4*)(Wptr + r * skipA);
        {
            float* as = As[0]; float* bs = Bs[0];
#pragma unroll
            for (int r = 0; r < 4; ++r) {
                as[(akc + 0) * SA + arow + 32 * r] = pa[r].x;
                as[(akc + 1) * SA + arow + 32 * r] = pa[r].y;
                as[(akc + 2) * SA + arow + 32 * r] = pa[r].z;
                as[(akc + 3) * SA + arow + 32 * r] = pa[r].w;
            }
#pragma unroll
            for (int r = 0; r < 2; ++r) {
                bs[(akc + 0) * SB + arow + 32 * r] = pb[r].x;
                bs[(akc + 1) * SB + arow + 32 * r] = pb[r].y;
                bs[(akc + 2) * SB + arow + 32 * r] = pb[r].z;
                bs[(akc + 3) * SB + arow + 32 * r] = pb[r].w;
            }
        }
        __syncthreads();

        for (int kt = 0; kt < nK; ++kt) {
            const int buf = kt & 1;

            if (kt + 1 < nK) {
                const int k0 = (kt + 1) * BK;
#pragma unroll
                for (int r = 0; r < 4; ++r) pa[r] = *(const float4*)(Aptr + r * skipA + k0);
#pragma unroll
                for (int r = 0; r < 2; ++r) pb[r] = *(const float4*)(Wptr + r * skipA + k0);
            }

            const float* as = As[buf];
            const float* bs = Bs[buf];
#pragma unroll 8
            for (int k = 0; k < BK; ++k) {
                float a[TM], b[TN];
                *(float4*)&a[0] = *(const float4*)&as[k * SA + ty * TM];
                *(float4*)&a[4] = *(const float4*)&as[k * SA + ty * TM + 4];
                *(float4*)&b[0] = *(const float4*)&bs[k * SB + tx * TN];
#pragma unroll
                for (int i = 0; i < TM; ++i)
#pragma unroll
                    for (int j = 0; j < TN; ++j) {
                        float p = a[i] * b[j];
                        mx[i][j] = fmaxf(mx[i][j], p);
                        mn[i][j] = fminf(mn[i][j], p);
                    }
            }

            if (kt + 1 < nK) {
                float* asw = As[buf ^ 1]; float* bsw = Bs[buf ^ 1];
#pragma unroll
                for (int r = 0; r < 4; ++r) {
                    asw[(akc + 0) * SA + arow + 32 * r] = pa[r].x;
                    asw[(akc + 1) * SA + arow + 32 * r] = pa[r].y;
                    asw[(akc + 2) * SA + arow + 32 * r] = pa[r].z;
                    asw[(akc + 3) * SA + arow + 32 * r] = pa[r].w;
                }
#pragma unroll
                for (int r = 0; r < 2; ++r) {
                    bsw[(akc + 0) * SB + arow + 32 * r] = pb[r].x;
                    bsw[(akc + 1) * SB + arow + 32 * r] = pb[r].y;
                    bsw[(akc + 2) * SB + arow + 32 * r] = pb[r].z;
                    bsw[(akc + 3) * SB + arow + 32 * r] = pb[r].w;
                }
                __syncthreads();
            }
        }

        // ---- epilogue: exclusive-owner partial stores ----
        const int row0 = mi * TBM + ty * TM;
        const int col0 = ni * TBN + tx * TN;
        float* mxp = g_mx[split] + (size_t)row0 * N + col0;
        float* mnp = g_mn[split] + (size_t)row0 * N + col0;
#pragma unroll
        for (int i = 0; i < TM; ++i) {
            *(float4*)(mxp + (size_t)i * N) = make_float4(mx[i][0], mx[i][1], mx[i][2], mx[i][3]);
            *(float4*)(mnp + (size_t)i * N) = make_float4(mn[i][0], mn[i][1], mn[i][2], mn[i][3]);
        }

        // ---- warp-granular arrival: no extra CTA syncs ----
        __threadfence();        // release this thread's partial stores (gpu scope)
        __syncwarp();           // whole warp's stores+fences done before lane0 arrives
        unsigned int old = 0;
        if (lane == 0) old = atomicAdd(&g_cnt[tile], 1u);
        old = __shfl_sync(0xFFFFFFFFu, old, 0);

        if (old >= WARPS_PER_TILE - 8) {
            // This warp is among the last 8 arrivals for this tile: all 32 warps'
            // partials are fenced-visible. Merge slice (old - 24) of the tile.
            __threadfence();    // acquire
            const int slice = old - (WARPS_PER_TILE - 8);   // 0..7
            const int rowbase = mi * TBM;
            const int colbase = ni * TBN;
            // slice = 16 rows x 64 cols = 1024 elems; per lane: 8 float4
#pragma unroll 2
            for (int it = 0; it < 8; ++it) {
                const int e = slice * 1024 + it * 128 + lane * 4;
                const int r = e >> 6;
                const int c = e & 63;
                const size_t off = (size_t)(rowbase + r) * N + colbase + c;

                float4 xm = *(const float4*)(g_mx[0] + off);
                float4 nm = *(const float4*)(g_mn[0] + off);
#pragma unroll
                for (int s = 1; s < SPLITS; ++s) {
                    float4 xs = *(const float4*)(g_mx[s] + off);
                    float4 ns = *(const float4*)(g_mn[s] + off);
                    xm.x = fmaxf(xm.x, xs.x); xm.y = fmaxf(xm.y, xs.y);
                    xm.z = fmaxf(xm.z, xs.z); xm.w = fmaxf(xm.w, xs.w);
                    nm.x = fminf(nm.x, ns.x); nm.y = fminf(nm.y, ns.y);
                    nm.z = fminf(nm.z, ns.z); nm.w = fminf(nm.w, ns.w);
                }
                float4 bv = *(const float4*)&bias[colbase + c];
                float4 o;
                o.x = xm.x + nm.x + bv.x;
                o.y = xm.y + nm.y + bv.y;
                o.z = xm.z + nm.z + bv.z;
                o.w = xm.w + nm.w + bv.w;
                *(float4*)(C + off) = o;
            }
            if (old == WARPS_PER_TILE - 1 && lane == 0)
                g_cnt[tile] = 0;     // reset for next graph replay
        }
        // smem reuse safety: next item's prologue stores into buf0 are preceded by
        // this item's last staging __syncthreads (kt=nK-2) which ordered all buf0
        // reads... and the prologue itself is followed by __syncthreads before any
        // compute; a fast warp cannot overwrite a buffer still being read because
        // the only unsynced window is after the final compute (buf1 at kt=nK-1),
        // and the next prologue writes buf0 only, then syncs.
    }
}

extern "C" void kernel_launch(void* const* d_in, const int* in_sizes, int n_in,
                              void* d_out, int out_size)
{
    const float* x    = (const float*)d_in[0];   // [M, K]
    const float* w    = (const float*)d_in[1];   // [N, K]
    const float* bias = (const float*)d_in[2];   // [N]
    float* out = (float*)d_out;

    const int N = in_sizes[2];                  // 1024
    const int K = in_sizes[1] / N;              // 1024
    const int M = in_sizes[0] / K;              // 2048

    mam_kernel<<<NUM_SMS, THREADS>>>(x, w, bias, out, M, N, K);
}

// round 12
// speedup vs baseline: 1.2398x; 1.0068x over previous
#include <cuda_runtime.h>
#include <math_constants.h>

// Split-K persistent MAM-GEMM (R7 base) + software-pipelined LDS operands.
// 256 tiles of 128x64 x 4 K-splits = 1024 items over 148 persistent CTAs
// (98.8% balance). TM8xTN4. Register double-buffering of a/b so each LDS
// issues a full k-step (96 math ops) before its first consumer.

#define TBM 128
#define TBN 64
#define BK  16
#define TM  8
#define TN  4
#define SA  132     // 132*4 % 16 == 0 -> LDS.128 aligned
#define SB  68      // 68*4  % 16 == 0 -> LDS.128 aligned
#define NUM_SMS 148
#define SPLITS  4
#define THREADS 256

#define MM 2048
#define NN 1024
#define NTILES ((MM / TBM) * (NN / TBN))   // 256

__device__ float g_mx[SPLITS][MM * NN];    // 32 MB
__device__ float g_mn[SPLITS][MM * NN];    // 32 MB
__device__ unsigned int g_cnt[NTILES];     // zeroed at load; finisher resets -> replay-safe

__global__ __launch_bounds__(THREADS, 1)
void mam_kernel(const float* __restrict__ A,    // [M, K]
                const float* __restrict__ W,    // [N, K]
                const float* __restrict__ bias, // [N]
                float* __restrict__ C,          // [M, N]
                int M, int N, int K)
{
    __shared__ float As[2][BK * SA];  // As[buf][k*SA + m]
    __shared__ float Bs[2][BK * SB];  // Bs[buf][k*SB + n]
    __shared__ unsigned int s_old;

    const int tid = threadIdx.x;
    const int tx  = tid & 15;    // 16 col-groups of TN=4 -> 64 cols
    const int ty  = tid >> 4;    // 16 row-groups of TM=8 -> 128 rows

    // A staging: 128x16 floats = 256 threads x 2 float4 (rows ar, ar+64)
    const int ar  = tid >> 2;         // 0..63
    const int akc = (tid & 3) * 4;    // 0,4,8,12
    // B staging: 64x16 floats = 256 threads x 1 float4
    const int br  = tid >> 2;         // 0..63
    const int bkc = (tid & 3) * 4;

    const int tilesN  = N / TBN;                  // 16
    const int nTiles  = (M / TBM) * tilesN;       // 256
    const int nItems  = nTiles * SPLITS;          // 1024
    const int kPart   = K / SPLITS;               // 256
    const int nK      = kPart / BK;               // 16

    for (int t = blockIdx.x; t < nItems; t += NUM_SMS) {
        const int tile  = t & (nTiles - 1);
        const int split = t >> 8;
        const int mi = tile >> 4;
        const int ni = tile & 15;
        const int kbase = split * kPart;

        const float* Aptr = A + (size_t)(mi * TBM + ar) * K + kbase + akc;
        const float* Wptr = W + (size_t)(ni * TBN + br) * K + kbase + bkc;
        const size_t arowskip = (size_t)64 * K;

        float mx[TM][TN], mn[TM][TN];
#pragma unroll
        for (int i = 0; i < TM; ++i)
#pragma unroll
            for (int j = 0; j < TN; ++j) {
                mx[i][j] = -CUDART_INF_F;
                mn[i][j] =  CUDART_INF_F;
            }

        // ---- prologue: stage k-slice 0 into buf 0 ----
        float4 pa0 = *(const float4*)(Aptr);
        float4 pa1 = *(const float4*)(Aptr + arowskip);
        float4 pb  = *(const float4*)(Wptr);
        {
            float* as = As[0]; float* bs = Bs[0];
            as[(akc + 0) * SA + ar] = pa0.x;
            as[(akc + 1) * SA + ar] = pa0.y;
            as[(akc + 2) * SA + ar] = pa0.z;
            as[(akc + 3) * SA + ar] = pa0.w;
            as[(akc + 0) * SA + ar + 64] = pa1.x;
            as[(akc + 1) * SA + ar + 64] = pa1.y;
            as[(akc + 2) * SA + ar + 64] = pa1.z;
            as[(akc + 3) * SA + ar + 64] = pa1.w;
            bs[(bkc + 0) * SB + br] = pb.x;
            bs[(bkc + 1) * SB + br] = pb.y;
            bs[(bkc + 2) * SB + br] = pb.z;
            bs[(bkc + 3) * SB + br] = pb.w;
        }
        __syncthreads();

        for (int kt = 0; kt < nK; ++kt) {
            const int buf = kt & 1;

            if (kt + 1 < nK) {
                const int k0 = (kt + 1) * BK;
                pa0 = *(const float4*)(Aptr + k0);
                pa1 = *(const float4*)(Aptr + arowskip + k0);
                pb  = *(const float4*)(Wptr + k0);
            }

            const float* as = As[buf];
            const float* bs = Bs[buf];

            // ---- software-pipelined compute: regs for k+1 load before k's math ----
            float a[2][TM], b[2][TN];
            *(float4*)&a[0][0] = *(const float4*)&as[ty * TM];
            *(float4*)&a[0][4] = *(const float4*)&as[ty * TM + 4];
            *(float4*)&b[0][0] = *(const float4*)&bs[tx * TN];
#pragma unroll
            for (int k = 0; k < BK; ++k) {
                const int cur = k & 1;
                if (k + 1 < BK) {
                    const int nxt = cur ^ 1;
                    *(float4*)&a[nxt][0] = *(const float4*)&as[(k + 1) * SA + ty * TM];
                    *(float4*)&a[nxt][4] = *(const float4*)&as[(k + 1) * SA + ty * TM + 4];
                    *(float4*)&b[nxt][0] = *(const float4*)&bs[(k + 1) * SB + tx * TN];
                }
#pragma unroll
                for (int i = 0; i < TM; ++i)
#pragma unroll
                    for (int j = 0; j < TN; ++j) {
                        float p = a[cur][i] * b[cur][j];
                        mx[i][j] = fmaxf(mx[i][j], p);
                        mn[i][j] = fminf(mn[i][j], p);
                    }
            }

            if (kt + 1 < nK) {
                float* asw = As[buf ^ 1]; float* bsw = Bs[buf ^ 1];
                asw[(akc + 0) * SA + ar] = pa0.x;
                asw[(akc + 1) * SA + ar] = pa0.y;
                asw[(akc + 2) * SA + ar] = pa0.z;
                asw[(akc + 3) * SA + ar] = pa0.w;
                asw[(akc + 0) * SA + ar + 64] = pa1.x;
                asw[(akc + 1) * SA + ar + 64] = pa1.y;
                asw[(akc + 2) * SA + ar + 64] = pa1.z;
                asw[(akc + 3) * SA + ar + 64] = pa1.w;
                bsw[(bkc + 0) * SB + br] = pb.x;
                bsw[(bkc + 1) * SB + br] = pb.y;
                bsw[(bkc + 2) * SB + br] = pb.z;
                bsw[(bkc + 3) * SB + br] = pb.w;
                __syncthreads();
            }
        }

        // ---- epilogue: exclusive-owner partial stores ----
        const int row0 = mi * TBM + ty * TM;
        const int col0 = ni * TBN + tx * TN;
        float* mxp = g_mx[split] + (size_t)row0 * N + col0;
        float* mnp = g_mn[split] + (size_t)row0 * N + col0;
#pragma unroll
        for (int i = 0; i < TM; ++i) {
            *(float4*)(mxp + (size_t)i * N) = make_float4(mx[i][0], mx[i][1], mx[i][2], mx[i][3]);
            *(float4*)(mnp + (size_t)i * N) = make_float4(mn[i][0], mn[i][1], mn[i][2], mn[i][3]);
        }

        // ---- arrival protocol ----
        __threadfence();                 // release partial stores (gpu scope)
        __syncthreads();                 // all threads' stores+fences done; orders smem reuse
        if (tid == 0) s_old = atomicAdd(&g_cnt[tile], 1u);
        __syncthreads();

        if (s_old == SPLITS - 1) {
            // ---- finisher: merge 4 partials + bias -> C ----
            __threadfence();             // acquire other CTAs' partials
            const int rowbase = mi * TBM;
            const int colbase = ni * TBN;
#pragma unroll
            for (int it = 0; it < 8; ++it) {
                const int e = it * 1024 + tid * 4;   // elem index within 128x64 tile
                const int r = e >> 6;
                const int c = e & 63;
                const size_t off = (size_t)(rowbase + r) * N + colbase + c;

                float4 x0 = *(const float4*)(g_mx[0] + off);
                float4 x1 = *(const float4*)(g_mx[1] + off);
                float4 x2 = *(const float4*)(g_mx[2] + off);
                float4 x3 = *(const float4*)(g_mx[3] + off);
                float4 n0 = *(const float4*)(g_mn[0] + off);
                float4 n1 = *(const float4*)(g_mn[1] + off);
                float4 n2 = *(const float4*)(g_mn[2] + off);
                float4 n3 = *(const float4*)(g_mn[3] + off);
                float4 bv = *(const float4*)&bias[colbase + c];

                float4 o;
                o.x = fmaxf(fmaxf(x0.x, x1.x), fmaxf(x2.x, x3.x)) + fminf(fminf(n0.x, n1.x), fminf(n2.x, n3.x)) + bv.x;
                o.y = fmaxf(fmaxf(x0.y, x1.y), fmaxf(x2.y, x3.y)) + fminf(fminf(n0.y, n1.y), fminf(n2.y, n3.y)) + bv.y;
                o.z = fmaxf(fmaxf(x0.z, x1.z), fmaxf(x2.z, x3.z)) + fminf(fminf(n0.z, n1.z), fminf(n2.z, n3.z)) + bv.z;
                o.w = fmaxf(fmaxf(x0.w, x1.w), fmaxf(x2.w, x3.w)) + fminf(fminf(n0.w, n1.w), fminf(n2.w, n3.w)) + bv.w;
                *(float4*)(C + off) = o;
            }
            if (tid == 0) g_cnt[tile] = 0;   // reset for next graph replay
        }
    }
}

extern "C" void kernel_launch(void* const* d_in, const int* in_sizes, int n_in,
                              void* d_out, int out_size)
{
    const float* x    = (const float*)d_in[0];   // [M, K]
    const float* w    = (const float*)d_in[1];   // [N, K]
    const float* bias = (const float*)d_in[2];   // [N]
    float* out = (float*)d_out;

    const int N = in_sizes[2];                  // 1024
    const int K = in_sizes[1] / N;              // 1024
    const int M = in_sizes[0] / K;              // 2048

    mam_kernel<<<NUM_SMS, THREADS>>>(x, w, bias, out, M, N, K);
}